// round 13
// baseline (speedup 1.0000x reference)
#include <cuda_runtime.h>

#define BB    32
#define NIN   2048
#define NHID  512
#define NOUT  10
#define TLEN  350
#define KSRM  100
#define KREF  32
#define THETA 10.0f
#define TT    25            // timesteps per GEMM1 window (350 = 14*25)
#define NWIN  (TLEN / TT)   // 14
#define NW    (NIN / 32)    // 64
#define HW    (NHID / 32)   // 16
#define CH    16            // weight rows per staged chunk
#define NCHK  (NIN / CH)    // 128
#define CC    25            // layer1 tile (100 = 4*25)
#define NCH   (TLEN / CC)   // 14
#define RING  5

// ---------------- device scratch ----------------
__device__ float    g_W1T[NIN * NHID];          // 4 MB, W1 transposed [n][m]
__device__ unsigned g_bits1[BB * TLEN * NW];    // packed spikes [b][t][w]
__device__ float    g_z1[BB * TLEN * NHID];     // [b][t][m]
__device__ unsigned g_s1b[BB * TLEN * HW];      // packed layer-1 spikes

extern __shared__ char sm_raw[];

// ---------------- K1: transpose W1 [NHID][NIN] -> [NIN][NHID] ------------
__global__ void k_transpose(const float* __restrict__ W1) {
    __shared__ float tile[32][33];
    int bx = blockIdx.x * 32, by = blockIdx.y * 32;
    int tx = threadIdx.x, ty = threadIdx.y;
    #pragma unroll
    for (int j = 0; j < 32; j += 8)
        tile[ty + j][tx] = W1[(by + ty + j) * NIN + bx + tx];
    __syncthreads();
    #pragma unroll
    for (int j = 0; j < 32; j += 8)
        g_W1T[(bx + ty + j) * NHID + (by + tx)] = tile[tx][ty + j];
}

// ---------------- K0: pack input spikes (float2 over t) ------------------
__global__ void k_pack(const float* __restrict__ x) {
    int b = blockIdx.y;
    int w = blockIdx.x;
    const float* xb = x + ((size_t)b * NIN + w * 32) * TLEN;
    for (int k = threadIdx.x; k < TLEN / 2; k += blockDim.x) {
        int t = k * 2;
        unsigned w0 = 0, w1 = 0;
        #pragma unroll
        for (int j = 0; j < 32; j++) {
            float2 v = *(const float2*)(xb + j * TLEN + t);
            w0 |= (v.x > 0.5f) ? (1u << j) : 0u;
            w1 |= (v.y > 0.5f) ? (1u << j) : 0u;
        }
        g_bits1[(b * TLEN + t    ) * NW + w] = w0;
        g_bits1[(b * TLEN + t + 1) * NW + w] = w1;
    }
}

// ---------------- dummy (ncu launch-slot alignment) ----------------------
__global__ void k_dummy() {}

// ---------------- K2: sparse GEMM, batch-paired CTAs ---------------------
// CTA = (window of 25 t, PAIR of batches). 256 threads: group tg=tid>>7 is
// the batch within the pair; each thread owns 4 adjacent m (float4),
// acc[25] float4. Weights staged ONCE per CTA serve both batches:
// 224 CTAs => weight L2 traffic halves vs R12 (0.9 GB, ~71 us floor).
__global__ __launch_bounds__(256, 2) void k_gemm1() {
    float*    stage = (float*)sm_raw;                          // [2][CH*NHID] 64 KB
    unsigned* colm  = (unsigned*)(sm_raw + 2 * CH * NHID * 4); // [2][TT][NW] 12.5 KB

    int bp   = blockIdx.y;        // batch pair index (0..15)
    int t0   = blockIdx.x * TT;
    int tid  = threadIdx.x;
    int tg   = tid >> 7;          // batch within pair
    int lid  = tid & 127;         // m-slot (owns m = 4*lid .. 4*lid+3)

    // column masks for both batches of the pair: layout [g][t][w]
    for (int i = tid; i < 2 * TT * NW; i += 256) {
        int g = i / (TT * NW), r = i - g * (TT * NW);
        colm[i] = g_bits1[((bp * 2 + g) * TLEN + t0) * NW + r];
    }

    float4 acc[TT];
    #pragma unroll
    for (int t = 0; t < TT; t++) acc[t] = make_float4(0.f, 0.f, 0.f, 0.f);

    const char* wsrc = (const char*)g_W1T;

    // cp.async copy of chunk c into buffer c&1 (8 x 16B per thread = 32 KB)
    #define ISSUE_CHUNK(c) do {                                              \
        unsigned _dst = (unsigned)__cvta_generic_to_shared(                  \
            stage + ((c) & 1) * (CH * NHID)) + tid * 16;                     \
        const char* _src = wsrc + (size_t)(c) * (CH * NHID * 4) + tid * 16;  \
        _Pragma("unroll")                                                    \
        for (int k = 0; k < 8; k++)                                          \
            asm volatile("cp.async.cg.shared.global [%0], [%1], 16;"         \
                         :: "r"(_dst + k * 4096), "l"(_src + k * 4096)       \
                         : "memory");                                        \
        asm volatile("cp.async.commit_group;" ::: "memory");                 \
    } while (0)

    ISSUE_CHUNK(0);

    for (int c = 0; c < NCHK; c++) {
        if (c) __syncthreads();            // everyone done reading buf (c+1)&1
        if (c + 1 < NCHK) {
            ISSUE_CHUNK(c + 1);
            asm volatile("cp.async.wait_group 1;" ::: "memory");
        } else {
            asm volatile("cp.async.wait_group 0;" ::: "memory");
        }
        __syncthreads();                   // chunk c (and colm on c==0) visible

        const float4*   st = (const float4*)(stage + (c & 1) * (CH * NHID)) + lid;
        const unsigned* cm = colm + tg * (TT * NW);
        int wi = c >> 1, sh = (c & 1) * 16;

        #pragma unroll
        for (int t = 0; t < TT; t++) {
            unsigned m = (cm[t * NW + wi] >> sh) & 0xFFFFu;
            while (m) {
                int j = __ffs(m) - 1; m &= m - 1;
                float4 wv = st[j * 128];   // LDS.128, conflict-free
                acc[t].x += wv.x;
                acc[t].y += wv.y;
                acc[t].z += wv.z;
                acc[t].w += wv.w;
            }
        }
    }
    #undef ISSUE_CHUNK

    float4* zo = (float4*)(g_z1 + ((size_t)(bp * 2 + tg) * TLEN + t0) * NHID);
    #pragma unroll
    for (int t = 0; t < TT; t++)
        zo[t * 128 + lid] = acc[t];        // coalesced 16B stores
}

// ---------------- K3: layer-1 SRM + spike (smem ring) --------------------
__global__ void k_layer1() {
    float* ring  = (float*)sm_raw;                  // [RING][CC*128]
    float* srefk = (float*)sm_raw + RING * CC * 128;

    int b   = blockIdx.y;
    int m0  = blockIdx.x * 128;
    int tid = threadIdx.x;
    if (tid < KREF)
        srefk[tid] = -2.0f * THETA * (float)tid * expf(1.0f - (float)tid);

    const float r    = expf(-0.1f);
    const float rK   = expf(-10.0f);
    const float KrK  = 100.0f * rK;
    const float Ceps = expf(1.0f) * 0.1f;

    const float* zb = g_z1 + (size_t)b * TLEN * NHID + m0;

    float A = 0.f, Y = 0.f;
    unsigned hist = 0;
    int wbase = (b * TLEN) * HW + (m0 >> 5) + (tid >> 5);

    for (int c = 0; c < NCH; c++) {
        float* tile = ring + (c % RING) * (CC * 128);
        __syncthreads();
        #pragma unroll
        for (int i = 0; i < CC; i++)
            tile[i * 128 + tid] = zb[(size_t)(c * CC + i) * NHID + tid];
        __syncthreads();

        const float* tprev = ring + ((c + 1) % RING) * (CC * 128); // slot c-4
        #pragma unroll
        for (int i = 0; i < CC; i++) {
            float xz = tile[i * 128 + tid];
            float xo = (c >= 4) ? tprev[i * 128 + tid] : 0.f;
            float Yn = r * (Y + A) - KrK * xo;
            A = r * A + xz - rK * xo;
            Y = Yn;
            float u = Ceps * Y;

            float refr = 0.f;
            unsigned hb = hist;
            while (hb) { int k = __ffs(hb) - 1; hb &= hb - 1; refr += srefk[k + 1]; }

            bool s = (u + refr >= THETA);
            hist = ((hist << 1) | (s ? 1u : 0u)) & 0x7FFFFFFFu;

            unsigned bal = __ballot_sync(0xFFFFFFFFu, s);
            if ((tid & 31) == 0)
                g_s1b[wbase + (c * CC + i) * HW] = bal;
        }
    }
}

// ---------------- K4: fused gemm2 + layer-2 SRM + spike ------------------
__global__ __launch_bounds__(352) void k_out(const float* __restrict__ W2,
                                             float* __restrict__ out) {
    __shared__ float w2t[NHID * NOUT];
    __shared__ float q[NOUT * TLEN];
    __shared__ float srefk[KREF];

    int b = blockIdx.x, tid = threadIdx.x;
    for (int i = tid; i < NHID * NOUT; i += blockDim.x) {
        int o = i / NHID, m = i % NHID;
        w2t[m * NOUT + o] = W2[i];
    }
    if (tid < KREF)
        srefk[tid] = -2.0f * THETA * (float)tid * expf(1.0f - (float)tid);
    __syncthreads();

    if (tid < TLEN) {
        int t = tid;
        float a[NOUT];
        #pragma unroll
        for (int o = 0; o < NOUT; o++) a[o] = 0.f;
        #pragma unroll
        for (int w = 0; w < HW; w++) {
            unsigned bits = g_s1b[(b * TLEN + t) * HW + w];
            while (bits) {
                int m = w * 32 + __ffs(bits) - 1;
                bits &= bits - 1;
                #pragma unroll
                for (int o = 0; o < NOUT; o++) a[o] += w2t[m * NOUT + o];
            }
        }
        #pragma unroll
        for (int o = 0; o < NOUT; o++) q[o * TLEN + t] = a[o];
    }
    __syncthreads();

    if (tid < NOUT) {
        const float r    = expf(-0.1f);
        const float rK   = expf(-10.0f);
        const float KrK  = 100.0f * rK;
        const float Ceps = expf(1.0f) * 0.1f;

        const float* qq = q + tid * TLEN;
        float* so = out + ((size_t)b * NOUT + tid) * TLEN;

        float A = 0.f, Y = 0.f;
        unsigned hist = 0;
        for (int t = 0; t < TLEN; t++) {
            float xz = qq[t];
            float xo = (t >= KSRM) ? qq[t - KSRM] : 0.f;
            float Yn = r * (Y + A) - KrK * xo;
            A = r * A + xz - rK * xo;
            Y = Yn;
            float u = Ceps * Y;

            float refr = 0.f;
            unsigned hb = hist;
            while (hb) { int k = __ffs(hb) - 1; hb &= hb - 1; refr += srefk[k + 1]; }

            bool s = (u + refr >= THETA);
            hist = ((hist << 1) | (s ? 1u : 0u)) & 0x7FFFFFFFu;
            so[t] = s ? 1.0f : 0.0f;
        }
    }
}

// ---------------- launch ----------------
extern "C" void kernel_launch(void* const* d_in, const int* in_sizes, int n_in,
                              void* d_out, int out_size) {
    const float* x  = (const float*)d_in[0];   // [32, 2048, 350]
    const float* W1 = (const float*)d_in[1];   // [512, 2048]
    const float* W2 = (const float*)d_in[2];   // [10, 512]
    float* out = (float*)d_out;                // [32, 10, 350]

    const int SMEM_G1 = 2 * CH * NHID * 4 + 2 * TT * NW * 4;  // 78,336 B
    const int SMEM_L1 = (RING * CC * 128 + KREF) * 4;         // 64,128 B
    cudaFuncSetAttribute(k_gemm1, cudaFuncAttributeMaxDynamicSharedMemorySize,
                         SMEM_G1);
    cudaFuncSetAttribute(k_layer1, cudaFuncAttributeMaxDynamicSharedMemorySize,
                         SMEM_L1);

    k_transpose<<<dim3(NIN / 32, NHID / 32), dim3(32, 8)>>>(W1);   // 1
    k_pack<<<dim3(NW, BB), 128>>>(x);                              // 2
    k_dummy<<<1, 32>>>();                                          // 3
    k_gemm1<<<dim3(NWIN, BB / 2), 256, SMEM_G1>>>();               // 4 (ncu slot)
    k_layer1<<<dim3(NHID / 128, BB), 128, SMEM_L1>>>();            // 5
    k_out<<<BB, 352>>>(W2, out);                                   // 6
}